// round 10
// baseline (speedup 1.0000x reference)
#include <cuda_runtime.h>
#include <cstdint>
#include <cstddef>

// Problem constants
#define B_TOT  131072
#define T_DIM  5
#define V_DIM  60
#define TV     300
#define KB     64                 // b-rows per k-tile
#define NC     296                // CTAs in kernel 1 (2 per SM)
#define NTILES (B_TOT / KB)       // 2048
#define NG     37                 // slab groups in k2a (37*8 = 296)

// Per-CTA partial M slabs, TRANSPOSED: part[c][j*60 + v] = M_c[v][j]
__device__ float g_part[NC * 3600];
// Group partials (k2a output): g_red[g][j*60+v], g = 0..36
__device__ float g_red[NG * 3600];

// Packed f32x2 FMA (sm_100+); scalar fallback otherwise. Same numerics (.rn).
__device__ __forceinline__ unsigned long long fma2(unsigned long long a,
                                                   unsigned long long b,
                                                   unsigned long long c) {
#if defined(__CUDA_ARCH__) && (__CUDA_ARCH__ >= 1000)
    unsigned long long d;
    asm("fma.rn.f32x2 %0, %1, %2, %3;" : "=l"(d) : "l"(a), "l"(b), "l"(c));
    return d;
#else
    float2 fa = *reinterpret_cast<float2*>(&a);
    float2 fb = *reinterpret_cast<float2*>(&b);
    float2 fc = *reinterpret_cast<float2*>(&c);
    float2 fd;
    fd.x = fmaf(fa.x, fb.x, fc.x);
    fd.y = fmaf(fa.y, fb.y, fc.y);
    return *reinterpret_cast<unsigned long long*>(&fd);
#endif
}

// ============================================================================
// Kernel 1: Phase A reads x from GMEM into registers (x passes l1tex once),
// computes a = x·W1, r = x·W3; stores:
//   sAd[k][2v]  A pre-DUPLICATED {a,a} pairs -> Phase B A-loads are LDS.128
//               4-address broadcasts, ZERO register-duplication MOVs
//   sR [k][swz] r with +4 offset for j>=32  -> r LDS.128 conflict-free
// Phase B: M += a ⊗ r, 32 f32x2 FMAs per k per thread.
// KB=64 + double buffer -> one barrier per 4096 fma-cycles of work.
// Dynamic smem: sAd[2][64*128] + sR[2][64*68] = 100352 B (x2 CTAs = 197 KB).
// ============================================================================
__global__ __launch_bounds__(256, 2)
void k1_gram(const float* __restrict__ x,
             const float* __restrict__ W1,
             const float* __restrict__ W3) {
    extern __shared__ float smem[];
    float* sAd[2] = { smem,               smem + KB * 128 };
    float* sR[2]  = { smem + 2 * KB * 128, smem + 2 * KB * 128 + KB * 68 };

    const int tid = threadIdx.x;

    float w1[T_DIM], w3[T_DIM];
#pragma unroll
    for (int t = 0; t < T_DIM; t++) { w1[t] = W1[t]; w3[t] = W3[t]; }

    // Phase-B mapping: 4 k-groups x (8x8 thread grid), 8x8 output per thread
    const int grp = tid >> 6;        // 0..3 : handles k = grp + 4*kk
    const int gt  = tid & 63;
    const int ty  = gt >> 3;         // rows  v = ty*8 + i
    const int tx  = gt & 7;          // cols  j = tx*8 + 2*jp + {0,1}
    const int rOff = tx * 8 + (tx >> 2) * 4;   // swizzled r base

    // Phase-A mapping: 16 b-rows x 16 v-lanes (lane 15 = zero pad), 4 passes
    const int rowA  = tid >> 4;      // 0..15
    const int laneA = tid & 15;      // 0..15
    const int roA   = (laneA >> 1) * 8 + (laneA & 1) * 4 + (laneA >> 3) * 4;

    unsigned long long acc[8][4];
#pragma unroll
    for (int i = 0; i < 8; i++)
#pragma unroll
        for (int jp = 0; jp < 4; jp++) acc[i][jp] = 0ull;

    auto phaseA = [&](int tile, int buf) {
#pragma unroll
        for (int p = 0; p < 4; p++) {
            const int k = rowA + 16 * p;             // 0..63
            float4 a4 = make_float4(0.f, 0.f, 0.f, 0.f);
            float4 r4 = make_float4(0.f, 0.f, 0.f, 0.f);
            if (laneA < 15) {
                const float* xb = x + (size_t)(tile * KB + k) * TV + laneA * 4;
#pragma unroll
                for (int t = 0; t < T_DIM; t++) {
                    float4 xv = *(const float4*)(xb + t * V_DIM);
                    a4.x = fmaf(xv.x, w1[t], a4.x); r4.x = fmaf(xv.x, w3[t], r4.x);
                    a4.y = fmaf(xv.y, w1[t], a4.y); r4.y = fmaf(xv.y, w3[t], r4.y);
                    a4.z = fmaf(xv.z, w1[t], a4.z); r4.z = fmaf(xv.z, w3[t], r4.z);
                    a4.w = fmaf(xv.w, w1[t], a4.w); r4.w = fmaf(xv.w, w3[t], r4.w);
                }
            }
            float* pd = &sAd[buf][k * 128 + laneA * 8];
            *(float4*)(pd)     = make_float4(a4.x, a4.x, a4.y, a4.y);
            *(float4*)(pd + 4) = make_float4(a4.z, a4.z, a4.w, a4.w);
            *(float4*)&sR[buf][k * 68 + roA] = r4;
        }
    };

    // Prologue: fill buffer 0
    phaseA(blockIdx.x, 0);
    __syncthreads();

    int buf = 0;
    for (int tile = blockIdx.x; tile < NTILES; tile += NC) {
        // ---------- Phase B on buf: 16 kk x 32 fma2 ----------
#pragma unroll
        for (int kk = 0; kk < KB / 4; kk++) {
            const int k = grp + kk * 4;
            unsigned long long ad[8];
            const ulonglong2* pa = (const ulonglong2*)&sAd[buf][k * 128 + ty * 16];
#pragma unroll
            for (int q = 0; q < 4; q++) {       // 4x LDS.128, 4-addr broadcast
                ulonglong2 v = pa[q];
                ad[2 * q] = v.x; ad[2 * q + 1] = v.y;
            }
            const ulonglong2* rb = (const ulonglong2*)&sR[buf][k * 68 + rOff];
            ulonglong2 r0 = rb[0];              // 2x LDS.128, conflict-free
            ulonglong2 r1 = rb[1];
            unsigned long long rp[4] = { r0.x, r0.y, r1.x, r1.y };
#pragma unroll
            for (int i = 0; i < 8; i++)
#pragma unroll
                for (int jp = 0; jp < 4; jp++)
                    acc[i][jp] = fma2(ad[i], rp[jp], acc[i][jp]);
        }

        // ---------- Phase A for next tile into the other buffer ----------
        const int nxt = tile + NC;
        if (nxt < NTILES) phaseA(nxt, buf ^ 1);
        __syncthreads();
        buf ^= 1;
    }

    // ---------- Reduce 4 k-groups into Ms (reuse sAd[0]: 64x64) ----------
    float* Ms = sAd[0];
    if (grp == 0) {
#pragma unroll
        for (int i = 0; i < 8; i++)
#pragma unroll
            for (int jp = 0; jp < 4; jp++) {
                unsigned int lo, hi;
                asm("mov.b64 {%0,%1}, %2;" : "=r"(lo), "=r"(hi) : "l"(acc[i][jp]));
                Ms[(ty * 8 + i) * 64 + tx * 8 + jp * 2]     = __uint_as_float(lo);
                Ms[(ty * 8 + i) * 64 + tx * 8 + jp * 2 + 1] = __uint_as_float(hi);
            }
    }
    __syncthreads();
#pragma unroll
    for (int g = 1; g < 4; g++) {
        if (grp == g) {
#pragma unroll
            for (int i = 0; i < 8; i++)
#pragma unroll
                for (int jp = 0; jp < 4; jp++) {
                    unsigned int lo, hi;
                    asm("mov.b64 {%0,%1}, %2;" : "=r"(lo), "=r"(hi) : "l"(acc[i][jp]));
                    Ms[(ty * 8 + i) * 64 + tx * 8 + jp * 2]     += __uint_as_float(lo);
                    Ms[(ty * 8 + i) * 64 + tx * 8 + jp * 2 + 1] += __uint_as_float(hi);
                }
        }
        __syncthreads();
    }

    // ---------- Store transposed slab: part[blk][j*60+v] = Ms[v][j] ----------
    float* dst = g_part + (size_t)blockIdx.x * 3600;
    for (int e = tid; e < 3600; e += 256) {
        const int j = e / 60;
        const int v = e - j * 60;
        dst[e] = Ms[v * 64 + j];
    }
}

// ============================================================================
// Kernel 2a: wide slab reduction 296 -> 37. grid (37, 15) x 240 = 555 CTAs;
// each thread: 8 fully independent coalesced loads (one L2 latency round).
// ============================================================================
__global__ __launch_bounds__(240)
void k2a_reduce() {
    const int cg = blockIdx.x;                       // 0..36
    const int e  = blockIdx.y * 240 + threadIdx.x;   // 0..3599
    const float* p = g_part + (size_t)cg * 8 * 3600 + e;
    float s0 = p[0]          + p[(size_t)1 * 3600];
    float s1 = p[(size_t)2 * 3600] + p[(size_t)3 * 3600];
    float s2 = p[(size_t)4 * 3600] + p[(size_t)5 * 3600];
    float s3 = p[(size_t)6 * 3600] + p[(size_t)7 * 3600];
    g_red[cg * 3600 + e] = (s0 + s1) + (s2 + s3);
}

// ============================================================================
// Kernel 2b: one CTA per output column j, 512 threads.
//   Stage 1: 8 lanes x 64 v sum the 37 group-partials (<=5 indep loads/lane).
//   Stage 2: Mcol -> W2^T dot -> sigmoid -> V_s dot -> column softmax.
// ============================================================================
__global__ __launch_bounds__(512)
void k2b_epilogue(const float* __restrict__ W2,
                  const float* __restrict__ b_s,
                  const float* __restrict__ V_s,
                  float* __restrict__ out) {
    const int j   = blockIdx.x;
    const int tid = threadIdx.x;
    const int cl  = tid >> 6;    // 0..7
    const int v   = tid & 63;    // 0..63

    __shared__ float red[64 * 8];
    __shared__ float Mcol[64];
    __shared__ float sig[64];
    __shared__ float sS[64];

    // Stage 1: groups g = cl, cl+8, ... < 37
    float s = 0.f;
    if (v < 60) {
        const float* p = g_red + j * 60 + v;
#pragma unroll
        for (int g = cl; g < NG; g += 8) s += p[(size_t)g * 3600];
    }
    red[v * 8 + cl] = s;
    __syncthreads();

    if (tid < 64) {
        float m = 0.f;
#pragma unroll
        for (int c2 = 0; c2 < 8; c2++) m += red[tid * 8 + c2];
        Mcol[tid] = m;
    }
    __syncthreads();

    // Stage 2: epilogue on 60 threads
    float sg = 0.f;
    if (tid < 60) {
        const int k = tid;
        float pr = 0.f;
#pragma unroll 4
        for (int vv = 0; vv < 60; vv++) pr = fmaf(W2[vv * 60 + k], Mcol[vv], pr);
        pr += b_s[k * 60 + j];
        sg = 1.f / (1.f + expf(-pr));
    }
    if (tid < 64) sig[tid] = sg;
    __syncthreads();

    float Si = 0.f;
    if (tid < 60) {
        const float4* vr = (const float4*)(V_s + tid * 60);  // 240B rows, aligned
#pragma unroll
        for (int q = 0; q < 15; q++) {
            float4 vx = vr[q];
            Si = fmaf(vx.x, sig[q * 4 + 0], Si);
            Si = fmaf(vx.y, sig[q * 4 + 1], Si);
            Si = fmaf(vx.z, sig[q * 4 + 2], Si);
            Si = fmaf(vx.w, sig[q * 4 + 3], Si);
        }
    }
    if (tid < 64) sS[tid] = (tid < 60) ? Si : -1e30f;
    __syncthreads();

    if (tid < 60) {
        float m = -1e30f;
#pragma unroll 4
        for (int i2 = 0; i2 < 60; i2++) m = fmaxf(m, sS[i2]);
        float sum = 0.f;
#pragma unroll 4
        for (int i2 = 0; i2 < 60; i2++) sum += expf(sS[i2] - m);
        out[tid * 60 + j] = expf(Si - m) / sum;
    }
}

// ============================================================================
extern "C" void kernel_launch(void* const* d_in, const int* in_sizes, int n_in,
                              void* d_out, int out_size) {
    const float* x   = (const float*)d_in[0];
    const float* W1  = (const float*)d_in[1];
    const float* W2  = (const float*)d_in[2];
    const float* W3  = (const float*)d_in[3];
    const float* b_s = (const float*)d_in[4];
    const float* V_s = (const float*)d_in[5];
    float* out = (float*)d_out;

    const int smem_bytes = (2 * KB * 128 + 2 * KB * 68) * 4;  // 100352 B
    cudaFuncSetAttribute(k1_gram, cudaFuncAttributeMaxDynamicSharedMemorySize,
                         smem_bytes);

    k1_gram<<<NC, 256, smem_bytes>>>(x, W1, W3);
    k2a_reduce<<<dim3(NG, 15), 240>>>();
    k2b_epilogue<<<V_DIM, 512>>>(W2, b_s, V_s, out);
}

// round 11
// speedup vs baseline: 1.2063x; 1.2063x over previous
#include <cuda_runtime.h>
#include <cstdint>
#include <cstddef>

// Problem constants
#define B_TOT  131072
#define T_DIM  5
#define V_DIM  60
#define TV     300
#define KB     32                 // b-rows per k-tile
#define NC     296                // CTAs in kernel 1
#define NTILES (B_TOT / KB)       // 4096

// Per-CTA partial M slabs, TRANSPOSED: part[c][j*60 + v] = M_c[v][j]
__device__ float g_part[NC * 3600];

// Packed f32x2 FMA (sm_100+); scalar fallback otherwise. Same numerics (.rn).
__device__ __forceinline__ unsigned long long fma2(unsigned long long a,
                                                   unsigned long long b,
                                                   unsigned long long c) {
#if defined(__CUDA_ARCH__) && (__CUDA_ARCH__ >= 1000)
    unsigned long long d;
    asm("fma.rn.f32x2 %0, %1, %2, %3;" : "=l"(d) : "l"(a), "l"(b), "l"(c));
    return d;
#else
    float2 fa = *reinterpret_cast<float2*>(&a);
    float2 fb = *reinterpret_cast<float2*>(&b);
    float2 fc = *reinterpret_cast<float2*>(&c);
    float2 fd;
    fd.x = fmaf(fa.x, fb.x, fc.x);
    fd.y = fmaf(fa.y, fb.y, fc.y);
    return *reinterpret_cast<unsigned long long*>(&fd);
#endif
}

// {f, f} packed into a 64-bit register pair
__device__ __forceinline__ unsigned long long dup2(float f) {
    unsigned long long r;
    asm("mov.b64 %0, {%1, %2};" : "=l"(r) : "f"(f), "f"(f));
    return r;
}

// ============================================================================
// Kernel 1: occupancy-first GEMM. Thread tile 8v x 4j, f32x2 pairs along v:
//   - acc = 16 u64 (32 regs)  -> fits 84-reg cap -> 3 CTAs/SM (24 warps)
//   - a operands are NATURAL smem pairs (LDS.128, broadcast, zero MOVs)
//   - r operands: one LDS.128 + 4 dup2 per kk
// 2 k-groups x 128 threads; KB=32 double-buffered; 1 barrier per tile.
// ============================================================================
__global__ __launch_bounds__(256, 3)
void k1_gram(const float* __restrict__ x,
             const float* __restrict__ W1,
             const float* __restrict__ W3) {
    __shared__ float sA[2][KB * 64];   // plain a  (16 KB total)
    __shared__ float sR[2][KB * 68];   // plain r, 68-float rows (17.4 KB)

    const int tid = threadIdx.x;

    float w1[T_DIM], w3[T_DIM];
#pragma unroll
    for (int t = 0; t < T_DIM; t++) { w1[t] = W1[t]; w3[t] = W3[t]; }

    // Phase-B mapping: 2 k-groups x (8 ty x 16 tx); tile 8v x 4j per thread
    const int grp = tid >> 7;        // 0..1 : handles k = grp + 2*kk
    const int gt  = tid & 127;
    const int ty  = gt >> 4;         // 0..7 : v = ty*8 + 2*vp + {0,1}
    const int tx  = gt & 15;         // 0..15: j = tx*4 + jj

    // Phase-A mapping: 16 b-rows x 16 v-lanes (lane 15 = zero pad), 2 passes
    const int rowA  = tid >> 4;      // 0..15
    const int laneA = tid & 15;      // 0..15

    unsigned long long acc[4][4];    // [vp][jj] -> 32 registers
#pragma unroll
    for (int vp = 0; vp < 4; vp++)
#pragma unroll
        for (int jj = 0; jj < 4; jj++) acc[vp][jj] = 0ull;

    auto phaseA = [&](int tile, int buf) {
#pragma unroll
        for (int p = 0; p < 2; p++) {
            const int k = rowA + 16 * p;             // 0..31
            float4 a4 = make_float4(0.f, 0.f, 0.f, 0.f);
            float4 r4 = make_float4(0.f, 0.f, 0.f, 0.f);
            if (laneA < 15) {
                const float* xb = x + (size_t)(tile * KB + k) * TV + laneA * 4;
#pragma unroll
                for (int t = 0; t < T_DIM; t++) {
                    float4 xv = *(const float4*)(xb + t * V_DIM);
                    a4.x = fmaf(xv.x, w1[t], a4.x); r4.x = fmaf(xv.x, w3[t], r4.x);
                    a4.y = fmaf(xv.y, w1[t], a4.y); r4.y = fmaf(xv.y, w3[t], r4.y);
                    a4.z = fmaf(xv.z, w1[t], a4.z); r4.z = fmaf(xv.z, w3[t], r4.z);
                    a4.w = fmaf(xv.w, w1[t], a4.w); r4.w = fmaf(xv.w, w3[t], r4.w);
                }
            }
            *(float4*)&sA[buf][k * 64 + laneA * 4] = a4;
            *(float4*)&sR[buf][k * 68 + laneA * 4] = r4;
        }
    };

    // Prologue
    phaseA(blockIdx.x, 0);
    __syncthreads();

    int buf = 0;
    for (int tile = blockIdx.x; tile < NTILES; tile += NC) {
        // ---------- Phase B on buf: 16 kk x 16 fma2 ----------
#pragma unroll
        for (int kk = 0; kk < KB / 2; kk++) {
            const int k = grp + kk * 2;
            const ulonglong2* pa = (const ulonglong2*)&sA[buf][k * 64 + ty * 8];
            ulonglong2 a01 = pa[0];              // {a0,a1},{a2,a3}  broadcast
            ulonglong2 a23 = pa[1];              // {a4,a5},{a6,a7}
            unsigned long long ap[4] = { a01.x, a01.y, a23.x, a23.y };
            float4 r4 = *(const float4*)&sR[buf][k * 68 + tx * 4];
            unsigned long long rp[4] = { dup2(r4.x), dup2(r4.y),
                                         dup2(r4.z), dup2(r4.w) };
#pragma unroll
            for (int vp = 0; vp < 4; vp++)
#pragma unroll
                for (int jj = 0; jj < 4; jj++)
                    acc[vp][jj] = fma2(ap[vp], rp[jj], acc[vp][jj]);
        }

        // ---------- Phase A for next tile into the other buffer ----------
        const int nxt = tile + NC;
        if (nxt < NTILES) phaseA(nxt, buf ^ 1);
        __syncthreads();
        buf ^= 1;
    }

    // ---------- Reduce the 2 k-groups into Ms (reuse sA: 4096 = 64x64) -----
    float* Ms = &sA[0][0];
    if (grp == 0) {
#pragma unroll
        for (int vp = 0; vp < 4; vp++)
#pragma unroll
            for (int jj = 0; jj < 4; jj++) {
                unsigned int lo, hi;
                asm("mov.b64 {%0,%1}, %2;" : "=r"(lo), "=r"(hi) : "l"(acc[vp][jj]));
                const int v = ty * 8 + vp * 2;
                const int j = tx * 4 + jj;
                Ms[v * 64 + j]       = __uint_as_float(lo);
                Ms[(v + 1) * 64 + j] = __uint_as_float(hi);
            }
    }
    __syncthreads();
    if (grp == 1) {
#pragma unroll
        for (int vp = 0; vp < 4; vp++)
#pragma unroll
            for (int jj = 0; jj < 4; jj++) {
                unsigned int lo, hi;
                asm("mov.b64 {%0,%1}, %2;" : "=r"(lo), "=r"(hi) : "l"(acc[vp][jj]));
                const int v = ty * 8 + vp * 2;
                const int j = tx * 4 + jj;
                Ms[v * 64 + j]       += __uint_as_float(lo);
                Ms[(v + 1) * 64 + j] += __uint_as_float(hi);
            }
    }
    __syncthreads();

    // ---------- Store transposed slab: part[blk][j*60+v] = Ms[v][j] ----------
    float* dst = g_part + (size_t)blockIdx.x * 3600;
    for (int e = tid; e < 3600; e += 256) {
        const int j = e / 60;
        const int v = e - j * 60;
        dst[e] = Ms[v * 64 + j];
    }
}

// ============================================================================
// Kernel 2 (fused, wide): one CTA per output column j, 1024 threads.
//   Stage 1: 16 c-lanes x 64 v; each thread sums ~19 INDEPENDENT slab loads.
//   Stage 2: Mcol -> W2^T dot -> sigmoid -> V_s dot -> column softmax.
// ============================================================================
__global__ __launch_bounds__(1024)
void k2_fused(const float* __restrict__ W2,
              const float* __restrict__ b_s,
              const float* __restrict__ V_s,
              float* __restrict__ out) {
    const int j   = blockIdx.x;
    const int tid = threadIdx.x;
    const int cl  = tid >> 6;    // 0..15
    const int v   = tid & 63;    // 0..63

    __shared__ float red[64 * 16];
    __shared__ float Mcol[64];
    __shared__ float sig[64];
    __shared__ float sS[64];

    // Stage 1: slabs c = cl, cl+16, ... < 296  (18 or 19 per lane)
    float s0 = 0.f, s1 = 0.f, s2 = 0.f, s3 = 0.f;
    if (v < 60) {
        const float* p = g_part + j * 60 + v;
        int g = cl;
        for (; g + 48 < NC; g += 64) {
            s0 += p[(size_t)(g)      * 3600];
            s1 += p[(size_t)(g + 16) * 3600];
            s2 += p[(size_t)(g + 32) * 3600];
            s3 += p[(size_t)(g + 48) * 3600];
        }
        for (; g < NC; g += 16) s0 += p[(size_t)g * 3600];
    }
    red[v * 16 + cl] = (s0 + s1) + (s2 + s3);
    __syncthreads();

    if (tid < 64) {
        float m = 0.f;
#pragma unroll
        for (int c2 = 0; c2 < 16; c2++) m += red[tid * 16 + c2];
        Mcol[tid] = m;
    }
    __syncthreads();

    // Stage 2: epilogue on 60 threads
    float sg = 0.f;
    if (tid < 60) {
        const int k = tid;
        float pr = 0.f;
#pragma unroll 4
        for (int vv = 0; vv < 60; vv++) pr = fmaf(W2[vv * 60 + k], Mcol[vv], pr);
        pr += b_s[k * 60 + j];
        sg = 1.f / (1.f + expf(-pr));
    }
    if (tid < 64) sig[tid] = sg;
    __syncthreads();

    float Si = 0.f;
    if (tid < 60) {
        const float4* vr = (const float4*)(V_s + tid * 60);  // 240B rows, aligned
#pragma unroll
        for (int q = 0; q < 15; q++) {
            float4 vx = vr[q];
            Si = fmaf(vx.x, sig[q * 4 + 0], Si);
            Si = fmaf(vx.y, sig[q * 4 + 1], Si);
            Si = fmaf(vx.z, sig[q * 4 + 2], Si);
            Si = fmaf(vx.w, sig[q * 4 + 3], Si);
        }
    }
    if (tid < 64) sS[tid] = (tid < 60) ? Si : -1e30f;
    __syncthreads();

    if (tid < 60) {
        float m = -1e30f;
#pragma unroll 4
        for (int i2 = 0; i2 < 60; i2++) m = fmaxf(m, sS[i2]);
        float sum = 0.f;
#pragma unroll 4
        for (int i2 = 0; i2 < 60; i2++) sum += expf(sS[i2] - m);
        out[tid * 60 + j] = expf(Si - m) / sum;
    }
}

// ============================================================================
extern "C" void kernel_launch(void* const* d_in, const int* in_sizes, int n_in,
                              void* d_out, int out_size) {
    const float* x   = (const float*)d_in[0];
    const float* W1  = (const float*)d_in[1];
    const float* W2  = (const float*)d_in[2];
    const float* W3  = (const float*)d_in[3];
    const float* b_s = (const float*)d_in[4];
    const float* V_s = (const float*)d_in[5];
    float* out = (float*)d_out;

    k1_gram<<<NC, 256>>>(x, W1, W3);
    k2_fused<<<V_DIM, 1024>>>(W2, b_s, V_s, out);
}